// round 12
// baseline (speedup 1.0000x reference)
#include <cuda_runtime.h>
#include <cuda_fp16.h>
#include <cstdint>
#include <math.h>

// Modulated weights as fp16 hi/lo planes: [b][var][cout=32][k=296(288+pad)]
__device__ unsigned short g_wB[8][2][32][296];

#define AYS   5280u      // A y-stride bytes: 66 x-slots * 80
#define BLD   592u       // B row stride bytes (296 fp16)
#define BPS   18944u     // B plane (variant) size: 32 * 592
#define BOFF  52800u     // B offset in smem (after 1 A plane of 10*AYS)
#define SMEM_BYTES (52800 + 37888)   // 90,688

__device__ __forceinline__ uint32_t smem_u32(const void* p) {
    uint32_t a;
    asm("{ .reg .u64 t; cvta.to.shared.u64 t, %1; cvt.u32.u64 %0, t; }"
        : "=r"(a) : "l"(p));
    return a;
}
__device__ __forceinline__ void ldsm4(uint32_t* r, uint32_t addr) {
    asm volatile("ldmatrix.sync.aligned.m8n8.x4.shared.b16 {%0,%1,%2,%3}, [%4];"
                 : "=r"(r[0]), "=r"(r[1]), "=r"(r[2]), "=r"(r[3]) : "r"(addr));
}
__device__ __forceinline__ void mma16816(float* d, const uint32_t* a,
                                         uint32_t b0, uint32_t b1) {
    asm volatile(
        "mma.sync.aligned.m16n8k16.row.col.f32.f16.f16.f32 "
        "{%0,%1,%2,%3},{%4,%5,%6,%7},{%8,%9},{%0,%1,%2,%3};"
        : "+f"(d[0]), "+f"(d[1]), "+f"(d[2]), "+f"(d[3])
        : "r"(a[0]), "r"(a[1]), "r"(a[2]), "r"(a[3]), "r"(b0), "r"(b1));
}

// ---------------------------------------------------------------------------
// Kernel 1: modulate + demodulate, emit fp16 hi/lo weight matrices.
// ---------------------------------------------------------------------------
__global__ void modw_kernel(const float* __restrict__ style,
                            const float* __restrict__ weight,
                            const float* __restrict__ mod_w,
                            const float* __restrict__ mod_b)
{
    const int b    = blockIdx.x;
    const int tid  = threadIdx.x;
    const int warp = tid >> 5;
    const int lane = tid & 31;

    __shared__ float s_s[32];
    __shared__ float s_d[32];

    const float mod_scale  = 1.0f / sqrtf(512.0f);
    const float conv_scale = 1.0f / sqrtf(288.0f);

    #pragma unroll
    for (int i = 0; i < 4; i++) {
        int cin = warp + 8 * i;
        float acc = 0.f;
        const float* st = style + b * 512;
        const float* mw = mod_w + cin * 512;
        for (int j = lane; j < 512; j += 32)
            acc += st[j] * mw[j];
        #pragma unroll
        for (int off = 16; off; off >>= 1)
            acc += __shfl_xor_sync(0xffffffffu, acc, off);
        if (lane == 0)
            s_s[cin] = acc * mod_scale + mod_b[cin];
    }
    __syncthreads();

    #pragma unroll
    for (int i = 0; i < 4; i++) {
        int cout = warp + 8 * i;
        float ss = 0.f;
        #pragma unroll
        for (int j = 0; j < 9; j++) {
            int f   = lane + 32 * j;
            int cin = f / 9;
            int t   = f % 9;
            float v = conv_scale * weight[(cout * 32 + cin) * 9 + t] * s_s[cin];
            ss += v * v;
        }
        #pragma unroll
        for (int off = 16; off; off >>= 1)
            ss += __shfl_xor_sync(0xffffffffu, ss, off);
        if (lane == 0)
            s_d[cout] = rsqrtf(ss + 1e-8f);
    }
    __syncthreads();

    for (int idx = tid; idx < 9216; idx += 256) {
        int t  = idx >> 10;
        int co = (idx >> 5) & 31;
        int ci = idx & 31;
        float w = conv_scale * weight[(co * 32 + ci) * 9 + t] * s_s[ci] * s_d[co];
        __half hi = __float2half_rn(w);
        __half lo = __float2half_rn(w - __half2float(hi));
        g_wB[b][0][co][t * 32 + ci] = __half_as_ushort(hi);
        g_wB[b][1][co][t * 32 + ci] = __half_as_ushort(lo);
    }
}

// ---------------------------------------------------------------------------
// Kernel 2: tensor-core conv (mma.sync fp16, 2-pass w hi/lo).
// Tile 64(W) x 8(H); 8 warps, warp = one row (4 m-tiles sharing B frags).
// grid = (8, 64, 8); block = 256; 2 CTAs/SM.
// ---------------------------------------------------------------------------
__global__ __launch_bounds__(256, 2)
void conv_kernel(const float* __restrict__ x, float* __restrict__ out)
{
    extern __shared__ unsigned char smem[];
    const int tid  = threadIdx.x;
    const int lane = tid & 31;
    const int warp = tid >> 5;
    const int b    = blockIdx.z;
    const int x0   = blockIdx.x * 64;
    const int y0   = blockIdx.y * 8;

    // ---- stage B (both variants, 37,888 B) ----
    {
        const uint4* src = (const uint4*)&g_wB[b][0][0][0];
        uint4* dst = (uint4*)(smem + BOFF);
        for (int i = tid; i < 37888 / 16; i += 256)
            dst[i] = src[i];
    }

    // ---- stage A halo 10 x 66 x 32cin as a single fp16 plane [y][x][cin] ----
    {
        const float* xb = x + (size_t)b * 32 * 262144;
        for (int e = tid; e < 10 * 32 * 66; e += 256) {
            int xi   = e % 66;
            int rest = e / 66;
            int cin  = rest & 31;
            int y    = rest >> 5;
            int gx = x0 - 1 + xi;
            int gy = y0 - 1 + y;
            float v = 0.f;
            if ((unsigned)gx < 512u && (unsigned)gy < 512u)
                v = xb[(size_t)cin * 262144 + (size_t)gy * 512 + gx];
            uint32_t off = (uint32_t)y * AYS + (uint32_t)xi * 80 + (uint32_t)cin * 2;
            *(unsigned short*)(smem + off) = __half_as_ushort(__float2half_rn(v));
        }
    }
    __syncthreads();

    const uint32_t sb = smem_u32(smem);
    const uint32_t aLane = (uint32_t)(((lane & 7) + ((lane >> 3) & 1) * 8) * 80
                                      + (lane >> 4) * 16);
    const uint32_t bLane = (uint32_t)((lane & 7) * BLD + (lane >> 3) * 16);

    const int y = warp;
    float d[4][4][4];
    #pragma unroll
    for (int mt = 0; mt < 4; mt++)
        #pragma unroll
        for (int nt = 0; nt < 4; nt++)
            #pragma unroll
            for (int r = 0; r < 4; r++)
                d[mt][nt][r] = 0.f;

    #pragma unroll 1
    for (int tap = 0; tap < 9; tap++) {
        const int ky = tap / 3;
        const int kx = tap - 3 * ky;

        uint32_t Bf[2][4][4];
        const uint32_t bB = sb + BOFF + (uint32_t)tap * 64 + bLane;
        #pragma unroll
        for (int v = 0; v < 2; v++)
            #pragma unroll
            for (int nt = 0; nt < 4; nt++)
                ldsm4(Bf[v][nt], bB + (uint32_t)v * BPS + (uint32_t)nt * 8 * BLD);

        const uint32_t aB = sb + (uint32_t)(y + ky) * AYS + (uint32_t)kx * 80 + aLane;
        #pragma unroll
        for (int mt = 0; mt < 4; mt++) {
            uint32_t Ah0[4], Ah1[4];
            const uint32_t ab = aB + (uint32_t)mt * (16 * 80);
            ldsm4(Ah0, ab);
            ldsm4(Ah1, ab + 32);
            #pragma unroll
            for (int nt = 0; nt < 4; nt++) {
                mma16816(d[mt][nt], Ah0, Bf[0][nt][0], Bf[0][nt][1]);
                mma16816(d[mt][nt], Ah1, Bf[0][nt][2], Bf[0][nt][3]);
                mma16816(d[mt][nt], Ah0, Bf[1][nt][0], Bf[1][nt][1]);
                mma16816(d[mt][nt], Ah1, Bf[1][nt][2], Bf[1][nt][3]);
            }
        }
    }

    // ---- store (direct) ----
    const int gy   = y0 + y;
    const int prow = lane >> 2;
    const int cob  = (lane & 3) * 2;
    #pragma unroll
    for (int mt = 0; mt < 4; mt++) {
        #pragma unroll
        for (int nt = 0; nt < 4; nt++) {
            int p  = x0 + mt * 16 + prow;
            int co = nt * 8 + cob;
            size_t o0 = (((size_t)(b * 32 + co) * 512) + gy) * 512 + p;
            out[o0]              = d[mt][nt][0];
            out[o0 + 262144]     = d[mt][nt][1];   // co+1
            out[o0 + 8]          = d[mt][nt][2];   // pixel row +8
            out[o0 + 262144 + 8] = d[mt][nt][3];
        }
    }
}

// ---------------------------------------------------------------------------
extern "C" void kernel_launch(void* const* d_in, const int* in_sizes, int n_in,
                              void* d_out, int out_size)
{
    const float* x      = (const float*)d_in[0];
    const float* style  = (const float*)d_in[1];
    const float* weight = (const float*)d_in[2];
    const float* mod_w  = (const float*)d_in[3];
    const float* mod_b  = (const float*)d_in[4];
    float* out = (float*)d_out;

    cudaFuncSetAttribute(conv_kernel,
                         cudaFuncAttributeMaxDynamicSharedMemorySize, SMEM_BYTES);

    modw_kernel<<<8, 256>>>(style, weight, mod_w, mod_b);

    dim3 grid(8, 64, 8);
    conv_kernel<<<grid, 256, SMEM_BYTES>>>(x, out);
}

// round 15
// speedup vs baseline: 1.3499x; 1.3499x over previous
#include <cuda_runtime.h>
#include <cuda_fp16.h>
#include <cstdint>
#include <math.h>

// Modulated weights, fp16: [b][cout=32][k=296(288+pad)]
__device__ unsigned short g_wB[8][32][296];

#define AYS   2720u      // A y-stride bytes: 34 x-slots * 80
#define BLD   592u       // B row stride bytes (296 fp16)
#define BOFF  27200u     // B offset in smem (after 1 A plane of 10*AYS)
#define SMEM_BYTES (27200 + 18944)   // 46,144

__device__ __forceinline__ uint32_t smem_u32(const void* p) {
    uint32_t a;
    asm("{ .reg .u64 t; cvta.to.shared.u64 t, %1; cvt.u32.u64 %0, t; }"
        : "=r"(a) : "l"(p));
    return a;
}
__device__ __forceinline__ void ldsm4(uint32_t* r, uint32_t addr) {
    asm volatile("ldmatrix.sync.aligned.m8n8.x4.shared.b16 {%0,%1,%2,%3}, [%4];"
                 : "=r"(r[0]), "=r"(r[1]), "=r"(r[2]), "=r"(r[3]) : "r"(addr));
}
__device__ __forceinline__ void mma16816(float* d, const uint32_t* a,
                                         uint32_t b0, uint32_t b1) {
    asm volatile(
        "mma.sync.aligned.m16n8k16.row.col.f32.f16.f16.f32 "
        "{%0,%1,%2,%3},{%4,%5,%6,%7},{%8,%9},{%0,%1,%2,%3};"
        : "+f"(d[0]), "+f"(d[1]), "+f"(d[2]), "+f"(d[3])
        : "r"(a[0]), "r"(a[1]), "r"(a[2]), "r"(a[3]), "r"(b0), "r"(b1));
}

// ---------------------------------------------------------------------------
// Kernel 1: modulate + demodulate, emit fp16 weight matrices.
// ---------------------------------------------------------------------------
__global__ void modw_kernel(const float* __restrict__ style,
                            const float* __restrict__ weight,
                            const float* __restrict__ mod_w,
                            const float* __restrict__ mod_b)
{
    const int b    = blockIdx.x;
    const int tid  = threadIdx.x;
    const int warp = tid >> 5;
    const int lane = tid & 31;

    __shared__ float s_s[32];
    __shared__ float s_d[32];

    const float mod_scale  = 1.0f / sqrtf(512.0f);
    const float conv_scale = 1.0f / sqrtf(288.0f);

    #pragma unroll
    for (int i = 0; i < 4; i++) {
        int cin = warp + 8 * i;
        float acc = 0.f;
        const float* st = style + b * 512;
        const float* mw = mod_w + cin * 512;
        for (int j = lane; j < 512; j += 32)
            acc += st[j] * mw[j];
        #pragma unroll
        for (int off = 16; off; off >>= 1)
            acc += __shfl_xor_sync(0xffffffffu, acc, off);
        if (lane == 0)
            s_s[cin] = acc * mod_scale + mod_b[cin];
    }
    __syncthreads();

    #pragma unroll
    for (int i = 0; i < 4; i++) {
        int cout = warp + 8 * i;
        float ss = 0.f;
        #pragma unroll
        for (int j = 0; j < 9; j++) {
            int f   = lane + 32 * j;
            int cin = f / 9;
            int t   = f % 9;
            float v = conv_scale * weight[(cout * 32 + cin) * 9 + t] * s_s[cin];
            ss += v * v;
        }
        #pragma unroll
        for (int off = 16; off; off >>= 1)
            ss += __shfl_xor_sync(0xffffffffu, ss, off);
        if (lane == 0)
            s_d[cout] = rsqrtf(ss + 1e-8f);
    }
    __syncthreads();

    for (int idx = tid; idx < 9216; idx += 256) {
        int t  = idx >> 10;
        int co = (idx >> 5) & 31;
        int ci = idx & 31;
        float w = conv_scale * weight[(co * 32 + ci) * 9 + t] * s_s[ci] * s_d[co];
        g_wB[b][co][t * 32 + ci] = __half_as_ushort(__float2half_rn(w));
    }
}

// ---------------------------------------------------------------------------
// Kernel 2: tensor-core conv (mma.sync fp16, single pass).
// Tile 32(W) x 8(H); 8 warps, warp = one row (2 m-tiles).
// grid = (16, 64, 8); block = 256; 3 CTAs/SM.
// ---------------------------------------------------------------------------
__global__ __launch_bounds__(256, 3)
void conv_kernel(const float* __restrict__ x, float* __restrict__ out)
{
    extern __shared__ unsigned char smem[];
    const int tid  = threadIdx.x;
    const int lane = tid & 31;
    const int warp = tid >> 5;
    const int b    = blockIdx.z;
    const int x0   = blockIdx.x * 32;
    const int y0   = blockIdx.y * 8;

    // ---- stage B (18,944 B) ----
    {
        const uint4* src = (const uint4*)&g_wB[b][0][0];
        uint4* dst = (uint4*)(smem + BOFF);
        for (int i = tid; i < 18944 / 16; i += 256)
            dst[i] = src[i];
    }

    // ---- stage A halo 10 x 34 x 32cin as a single fp16 plane [y][x][cin] ----
    {
        const float* xb = x + (size_t)b * 32 * 262144;
        for (int e = tid; e < 10 * 32 * 34; e += 256) {
            int xi   = e % 34;
            int rest = e / 34;
            int cin  = rest & 31;
            int y    = rest >> 5;
            int gx = x0 - 1 + xi;
            int gy = y0 - 1 + y;
            float v = 0.f;
            if ((unsigned)gx < 512u && (unsigned)gy < 512u)
                v = xb[(size_t)cin * 262144 + (size_t)gy * 512 + gx];
            uint32_t off = (uint32_t)y * AYS + (uint32_t)xi * 80 + (uint32_t)cin * 2;
            *(unsigned short*)(smem + off) = __half_as_ushort(__float2half_rn(v));
        }
    }
    __syncthreads();

    const uint32_t sb = smem_u32(smem);
    const uint32_t aLane = (uint32_t)(((lane & 7) + ((lane >> 3) & 1) * 8) * 80
                                      + (lane >> 4) * 16);
    const uint32_t bLane = (uint32_t)((lane & 7) * BLD + (lane >> 3) * 16);

    const int y = warp;
    float d[2][4][4];
    #pragma unroll
    for (int mt = 0; mt < 2; mt++)
        #pragma unroll
        for (int nt = 0; nt < 4; nt++)
            #pragma unroll
            for (int r = 0; r < 4; r++)
                d[mt][nt][r] = 0.f;

    #pragma unroll 1
    for (int tap = 0; tap < 9; tap++) {
        const int ky = tap / 3;
        const int kx = tap - 3 * ky;

        uint32_t Bf[4][4];
        const uint32_t bB = sb + BOFF + (uint32_t)tap * 64 + bLane;
        #pragma unroll
        for (int nt = 0; nt < 4; nt++)
            ldsm4(Bf[nt], bB + (uint32_t)nt * 8 * BLD);

        const uint32_t aB = sb + (uint32_t)(y + ky) * AYS + (uint32_t)kx * 80 + aLane;
        #pragma unroll
        for (int mt = 0; mt < 2; mt++) {
            uint32_t Ah0[4], Ah1[4];
            const uint32_t ab = aB + (uint32_t)mt * (16 * 80);
            ldsm4(Ah0, ab);
            ldsm4(Ah1, ab + 32);
            #pragma unroll
            for (int nt = 0; nt < 4; nt++) {
                mma16816(d[mt][nt], Ah0, Bf[nt][0], Bf[nt][1]);
                mma16816(d[mt][nt], Ah1, Bf[nt][2], Bf[nt][3]);
            }
        }
    }

    // ---- store (direct) ----
    const int gy   = y0 + y;
    const int prow = lane >> 2;
    const int cob  = (lane & 3) * 2;
    #pragma unroll
    for (int mt = 0; mt < 2; mt++) {
        #pragma unroll
        for (int nt = 0; nt < 4; nt++) {
            int p  = x0 + mt * 16 + prow;
            int co = nt * 8 + cob;
            size_t o0 = (((size_t)(b * 32 + co) * 512) + gy) * 512 + p;
            out[o0]              = d[mt][nt][0];
            out[o0 + 262144]     = d[mt][nt][1];   // co+1
            out[o0 + 8]          = d[mt][nt][2];   // pixel row +8
            out[o0 + 262144 + 8] = d[mt][nt][3];
        }
    }
}

// ---------------------------------------------------------------------------
extern "C" void kernel_launch(void* const* d_in, const int* in_sizes, int n_in,
                              void* d_out, int out_size)
{
    const float* x      = (const float*)d_in[0];
    const float* style  = (const float*)d_in[1];
    const float* weight = (const float*)d_in[2];
    const float* mod_w  = (const float*)d_in[3];
    const float* mod_b  = (const float*)d_in[4];
    float* out = (float*)d_out;

    cudaFuncSetAttribute(conv_kernel,
                         cudaFuncAttributeMaxDynamicSharedMemorySize, SMEM_BYTES);

    modw_kernel<<<8, 256>>>(style, weight, mod_w, mod_b);

    dim3 grid(16, 64, 8);
    conv_kernel<<<grid, 256, SMEM_BYTES>>>(x, out);
}